// round 12
// baseline (speedup 1.0000x reference)
#include <cuda_runtime.h>
#include <cuda_bf16.h>
#include <cstdint>

#define NN     40000
#define EE     640000
#define HH     128
#define GG     256
#define OUTD   10

#define SCAN_T 1024
#define SCAN_B ((NN + SCAN_T - 1) / SCAN_T)   // 40 blocks

// GEMM (tensor-core) geometry: 512 threads, 128x128 tile, warp tile 32x32
#define WS2 136                                // W smem stride (conflict-free B frags)
#define AS2 132                                // A smem stride (conflict-free A frags)
#define SMEM_WH_FLOATS (128 * WS2)
#define SMEM_A_FLOATS  (128 * AS2)
#define GEMM_SMEM_BYTES ((2 * SMEM_WH_FLOATS + SMEM_A_FLOATS) * 4)   // 206,848 B

// ---------------- scratch (no allocations allowed) ----------------
__device__ float g_bufA[(size_t)NN * HH];   // xw
__device__ float g_bufB[(size_t)NN * HH];   // h1
__device__ float g_dinv[NN];
__device__ int   g_degi[NN];
__device__ int   g_off[NN + 1];
__device__ int   g_cur[NN];
__device__ int   g_csrc[EE];
__device__ int   g_bsum[SCAN_B];
__device__ float g_sums[GG * HH];
__device__ float g_cnt[GG];

// ---------------- cp.async helpers ----------------
__device__ __forceinline__ void cp_async16(void* smem, const void* gmem) {
    unsigned s = (unsigned)__cvta_generic_to_shared(smem);
    asm volatile("cp.async.ca.shared.global [%0], [%1], 16;" :: "r"(s), "l"(gmem));
}
__device__ __forceinline__ void cp_commit() {
    asm volatile("cp.async.commit_group;" ::: "memory");
}
template <int N>
__device__ __forceinline__ void cp_wait() {
    asm volatile("cp.async.wait_group %0;" :: "n"(N) : "memory");
}

// ---------------- tf32 helpers ----------------
__device__ __forceinline__ unsigned f2tf32(float x) {
    unsigned r;
    asm("cvt.rna.tf32.f32 %0, %1;" : "=r"(r) : "f"(x));
    return r;
}
__device__ __forceinline__ void mma_tf32(float c[4], const unsigned a[4], const unsigned b[2]) {
    asm volatile(
        "mma.sync.aligned.m16n8k8.row.col.f32.tf32.tf32.f32 "
        "{%0,%1,%2,%3}, {%4,%5,%6,%7}, {%8,%9}, {%0,%1,%2,%3};"
        : "+f"(c[0]), "+f"(c[1]), "+f"(c[2]), "+f"(c[3])
        : "r"(a[0]), "r"(a[1]), "r"(a[2]), "r"(a[3]), "r"(b[0]), "r"(b[1]));
}

// ---------------- setup ----------------
__global__ void zero_k(int* degi, int* cur, float* sums, float* cnt) {
    int i = blockIdx.x * blockDim.x + threadIdx.x;
    if (i < NN) { degi[i] = 0; cur[i] = 0; }
    if (i < GG * HH) sums[i] = 0.0f;
    if (i < GG) cnt[i] = 0.0f;
}

__global__ void count_k(const int* __restrict__ col, int* degi) {
    int e = blockIdx.x * blockDim.x + threadIdx.x;
    if (e < EE) atomicAdd(&degi[col[e]], 1);
}

__global__ void dinv_cnt_k(const int* __restrict__ degi, float* __restrict__ dinv,
                           const int* __restrict__ batch, float* cnt) {
    int i = blockIdx.x * blockDim.x + threadIdx.x;
    if (i < NN) {
        dinv[i] = rsqrtf((float)(degi[i] + 1));   // +1 self-loop
        atomicAdd(&cnt[batch[i]], 1.0f);
    }
}

// ---------------- multi-block exclusive scan ----------------
__global__ __launch_bounds__(SCAN_T)
void scan1_k(const int* __restrict__ deg, int* __restrict__ off, int* __restrict__ bsum) {
    __shared__ int wsum[32];
    int tid = threadIdx.x, lane = tid & 31, wid = tid >> 5;
    int i = blockIdx.x * SCAN_T + tid;
    int v = (i < NN) ? deg[i] : 0;
    int x = v;
    #pragma unroll
    for (int o = 1; o < 32; o <<= 1) {
        int t = __shfl_up_sync(0xffffffffu, x, o);
        if (lane >= o) x += t;
    }
    if (lane == 31) wsum[wid] = x;
    __syncthreads();
    if (wid == 0) {
        int y = wsum[lane];
        #pragma unroll
        for (int o = 1; o < 32; o <<= 1) {
            int t = __shfl_up_sync(0xffffffffu, y, o);
            if (lane >= o) y += t;
        }
        wsum[lane] = y;
    }
    __syncthreads();
    int incl = x + (wid ? wsum[wid - 1] : 0);
    if (i < NN) off[i + 1] = incl;
    if (tid == SCAN_T - 1) bsum[blockIdx.x] = incl;
}

__global__ void scan2_k(int* __restrict__ bsum) {
    int lane = threadIdx.x & 31;
    int i0 = lane, i1 = lane + 32;
    int v0 = (i0 < SCAN_B) ? bsum[i0] : 0;
    int v1 = (i1 < SCAN_B) ? bsum[i1] : 0;
    int x0 = v0;
    #pragma unroll
    for (int o = 1; o < 32; o <<= 1) {
        int t = __shfl_up_sync(0xffffffffu, x0, o);
        if (lane >= o) x0 += t;
    }
    int tot0 = __shfl_sync(0xffffffffu, x0, 31);
    int x1 = v1;
    #pragma unroll
    for (int o = 1; o < 32; o <<= 1) {
        int t = __shfl_up_sync(0xffffffffu, x1, o);
        if (lane >= o) x1 += t;
    }
    if (i0 < SCAN_B) bsum[i0] = x0 - v0;
    if (i1 < SCAN_B) bsum[i1] = x1 - v1 + tot0;
}

__global__ __launch_bounds__(SCAN_T)
void scan3_k(int* __restrict__ off, const int* __restrict__ bsum) {
    int i = blockIdx.x * SCAN_T + threadIdx.x;
    if (i == 0) off[0] = 0;
    if (i < NN) off[i + 1] += bsum[blockIdx.x];
}

__global__ void scatter_k(const int* __restrict__ row, const int* __restrict__ col,
                          const int* __restrict__ off, int* cur, int* __restrict__ csrc) {
    int e = blockIdx.x * blockDim.x + threadIdx.x;
    if (e >= EE) return;
    int c = col[e];
    int pos = off[c] + atomicAdd(&cur[c], 1);
    csrc[pos] = row[e];
}

// ---------------- 3xTF32 tensor-core GEMM: xw = (relu?)A @ W ----------------
// 512 threads, 128x128 tile, warp tile 32x32 (2 m-tiles x 4 n-tiles).
// W pre-converted ONCE to tf32 hi/lo planes in smem; A fully resident; no mainloop syncs.
template <int RELU>
__global__ __launch_bounds__(512)
void gemm_tc_k(const float* __restrict__ A, const float* __restrict__ W,
               float* __restrict__ xw) {
    extern __shared__ float smem[];
    float* Whi = smem;                          // [128][WS2]
    float* Wlo = smem + SMEM_WH_FLOATS;         // [128][WS2]
    float* As  = smem + 2 * SMEM_WH_FLOATS;     // [128][AS2]

    const int tid  = threadIdx.x;
    const int warp = tid >> 5;
    const int lane = tid & 31;
    const int gid  = lane >> 2;                 // 0..7
    const int tig  = lane & 3;                  // 0..3
    const int mBase = (warp & 3) * 32;
    const int nBase = (warp >> 2) * 32;
    const int rowG  = blockIdx.x * 128;

    // stage raw W into Whi (group 0): 4096 float4, 8/thread
    #pragma unroll
    for (int i = 0; i < 8; i++) {
        int id = tid + i * 512;
        int r  = id >> 5;
        int c4 = (id & 31) * 4;
        cp_async16(&Whi[r * WS2 + c4], &W[r * 128 + c4]);
    }
    cp_commit();
    // stage A into As (group 1): 4096 float4, 8/thread
    #pragma unroll
    for (int i = 0; i < 8; i++) {
        int id = tid + i * 512;
        int r  = id >> 5;
        int c4 = (id & 31) * 4;
        int gr = rowG + r; if (gr > NN - 1) gr = NN - 1;
        cp_async16(&As[r * AS2 + c4], &A[(size_t)gr * HH + c4]);
    }
    cp_commit();

    cp_wait<1>();              // W staged
    __syncthreads();
    // convert W in place -> Whi (tf32-rounded) + Wlo (tf32 of residual); 32 elems/thread
    #pragma unroll
    for (int i = 0; i < 32; i++) {
        int id = tid + i * 512;
        int r  = id >> 7;
        int c  = id & 127;
        float v  = Whi[r * WS2 + c];
        unsigned hb = f2tf32(v);
        float hf = __uint_as_float(hb);
        Whi[r * WS2 + c] = hf;
        Wlo[r * WS2 + c] = __uint_as_float(f2tf32(v - hf));
    }
    cp_wait<0>();              // A staged
    __syncthreads();           // W converted + A visible to all

    float c[2][4][4];
    #pragma unroll
    for (int mt = 0; mt < 2; mt++)
        #pragma unroll
        for (int nt = 0; nt < 4; nt++)
            #pragma unroll
            for (int j = 0; j < 4; j++) c[mt][nt][j] = 0.0f;

    #pragma unroll
    for (int ks = 0; ks < 16; ks++) {
        int k0 = ks * 8;
        unsigned ahi[2][4], alo[2][4];
        #pragma unroll
        for (int mt = 0; mt < 2; mt++) {
            int r0 = mBase + mt * 16;
            float a0 = As[(r0 + gid)     * AS2 + k0 + tig];
            float a1 = As[(r0 + gid + 8) * AS2 + k0 + tig];
            float a2 = As[(r0 + gid)     * AS2 + k0 + tig + 4];
            float a3 = As[(r0 + gid + 8) * AS2 + k0 + tig + 4];
            if (RELU) {
                a0 = fmaxf(a0, 0.0f); a1 = fmaxf(a1, 0.0f);
                a2 = fmaxf(a2, 0.0f); a3 = fmaxf(a3, 0.0f);
            }
            ahi[mt][0] = f2tf32(a0); alo[mt][0] = f2tf32(a0 - __uint_as_float(ahi[mt][0]));
            ahi[mt][1] = f2tf32(a1); alo[mt][1] = f2tf32(a1 - __uint_as_float(ahi[mt][1]));
            ahi[mt][2] = f2tf32(a2); alo[mt][2] = f2tf32(a2 - __uint_as_float(ahi[mt][2]));
            ahi[mt][3] = f2tf32(a3); alo[mt][3] = f2tf32(a3 - __uint_as_float(ahi[mt][3]));
        }
        #pragma unroll
        for (int nt = 0; nt < 4; nt++) {
            int n0 = nBase + nt * 8;
            unsigned bhi[2], blo[2];
            bhi[0] = __float_as_uint(Whi[(k0 + tig)     * WS2 + n0 + gid]);
            bhi[1] = __float_as_uint(Whi[(k0 + tig + 4) * WS2 + n0 + gid]);
            blo[0] = __float_as_uint(Wlo[(k0 + tig)     * WS2 + n0 + gid]);
            blo[1] = __float_as_uint(Wlo[(k0 + tig + 4) * WS2 + n0 + gid]);
            #pragma unroll
            for (int mt = 0; mt < 2; mt++) {
                mma_tf32(c[mt][nt], ahi[mt], bhi);   // hi*hi
                mma_tf32(c[mt][nt], alo[mt], bhi);   // lo*hi
                mma_tf32(c[mt][nt], ahi[mt], blo);   // hi*lo
            }
        }
    }

    // epilogue
    #pragma unroll
    for (int mt = 0; mt < 2; mt++) {
        #pragma unroll
        for (int nt = 0; nt < 4; nt++) {
            int r0  = rowG + mBase + mt * 16 + gid;
            int col = nBase + nt * 8 + tig * 2;
            if (r0 < NN)
                *reinterpret_cast<float2*>(&xw[(size_t)r0 * HH + col]) =
                    make_float2(c[mt][nt][0], c[mt][nt][1]);
            int r1 = r0 + 8;
            if (r1 < NN)
                *reinterpret_cast<float2*>(&xw[(size_t)r1 * HH + col]) =
                    make_float2(c[mt][nt][2], c[mt][nt][3]);
        }
    }
}

// ---------------- node aggregation (warp per node, register accumulate) ----------------
template <int POOL>
__global__ __launch_bounds__(256)
void agg_node_k(const float* __restrict__ xw, const float* __restrict__ dinv,
                const int* __restrict__ off, const int* __restrict__ csrc,
                const float* __restrict__ bias, float* __restrict__ h,
                const int* __restrict__ batch, float* __restrict__ sums) {
    int n    = (blockIdx.x * blockDim.x + threadIdx.x) >> 5;
    int lane = threadIdx.x & 31;
    if (n >= NN) return;

    float dn = __ldg(&dinv[n]);
    float4 acc = *reinterpret_cast<const float4*>(xw + (size_t)n * HH + lane * 4);
    acc.x *= dn; acc.y *= dn; acc.z *= dn; acc.w *= dn;

    int p = __ldg(&off[n]);
    int e = __ldg(&off[n + 1]);

    for (; p + 1 < e; p += 2) {
        int s0 = __ldg(&csrc[p]);
        int s1 = __ldg(&csrc[p + 1]);
        float w0 = __ldg(&dinv[s0]);
        float w1 = __ldg(&dinv[s1]);
        float4 v0 = *reinterpret_cast<const float4*>(xw + (size_t)s0 * HH + lane * 4);
        float4 v1 = *reinterpret_cast<const float4*>(xw + (size_t)s1 * HH + lane * 4);
        acc.x += v0.x * w0 + v1.x * w1;
        acc.y += v0.y * w0 + v1.y * w1;
        acc.z += v0.z * w0 + v1.z * w1;
        acc.w += v0.w * w0 + v1.w * w1;
    }
    if (p < e) {
        int s0 = __ldg(&csrc[p]);
        float w0 = __ldg(&dinv[s0]);
        float4 v0 = *reinterpret_cast<const float4*>(xw + (size_t)s0 * HH + lane * 4);
        acc.x += v0.x * w0; acc.y += v0.y * w0;
        acc.z += v0.z * w0; acc.w += v0.w * w0;
    }

    float4 b = *reinterpret_cast<const float4*>(bias + lane * 4);
    float4 o;
    o.x = fmaf(acc.x, dn, b.x); o.y = fmaf(acc.y, dn, b.y);
    o.z = fmaf(acc.z, dn, b.z); o.w = fmaf(acc.w, dn, b.w);

    if (POOL) {
        o.x = fmaxf(o.x, 0.0f); o.y = fmaxf(o.y, 0.0f);
        o.z = fmaxf(o.z, 0.0f); o.w = fmaxf(o.w, 0.0f);
        int g = __ldg(&batch[n]);
        float* d = sums + (size_t)g * HH + lane * 4;
        asm volatile("red.global.add.v4.f32 [%0], {%1,%2,%3,%4};"
                     :: "l"(d), "f"(o.x), "f"(o.y), "f"(o.z), "f"(o.w) : "memory");
    } else {
        *reinterpret_cast<float4*>(h + (size_t)n * HH + lane * 4) = o;
    }
}

// ---------------- head: mean -> FC -> log_softmax ----------------
__global__ void head_k(const float* __restrict__ sums, const float* __restrict__ cnt,
                       const float* __restrict__ Wfc, const float* __restrict__ bfc,
                       float* __restrict__ out) {
    int g = blockIdx.x;
    int lane = threadIdx.x;
    float inv = 1.0f / fmaxf(cnt[g], 1.0f);
    float p[4];
    #pragma unroll
    for (int i = 0; i < 4; i++)
        p[i] = sums[(size_t)g * HH + lane * 4 + i] * inv;

    float logits[OUTD];
    #pragma unroll
    for (int o = 0; o < OUTD; o++) {
        float s = 0.0f;
        #pragma unroll
        for (int i = 0; i < 4; i++)
            s = fmaf(p[i], __ldg(&Wfc[(size_t)(lane * 4 + i) * OUTD + o]), s);
        #pragma unroll
        for (int off = 16; off > 0; off >>= 1)
            s += __shfl_xor_sync(0xffffffffu, s, off);
        logits[o] = s + __ldg(&bfc[o]);
    }
    if (lane == 0) {
        float m = logits[0];
        #pragma unroll
        for (int o = 1; o < OUTD; o++) m = fmaxf(m, logits[o]);
        float lse = 0.0f;
        #pragma unroll
        for (int o = 0; o < OUTD; o++) lse += expf(logits[o] - m);
        lse = logf(lse);
        #pragma unroll
        for (int o = 0; o < OUTD; o++)
            out[(size_t)g * OUTD + o] = logits[o] - m - lse;
    }
}

// ---------------- launcher ----------------
extern "C" void kernel_launch(void* const* d_in, const int* in_sizes, int n_in,
                              void* d_out, int out_size) {
    const float* x    = (const float*)d_in[0];
    const int*   ei   = (const int*)d_in[1];
    const int*   batch= (const int*)d_in[2];
    const float* W1   = (const float*)d_in[3];
    const float* b1   = (const float*)d_in[4];
    const float* W2   = (const float*)d_in[5];
    const float* b2   = (const float*)d_in[6];
    const float* Wfc  = (const float*)d_in[7];
    const float* bfc  = (const float*)d_in[8];
    float* out = (float*)d_out;

    const int* row = ei;
    const int* col = ei + EE;

    float* bufA = nullptr; cudaGetSymbolAddress((void**)&bufA, g_bufA);
    float* bufB = nullptr; cudaGetSymbolAddress((void**)&bufB, g_bufB);
    float* dinv = nullptr; cudaGetSymbolAddress((void**)&dinv, g_dinv);
    int*   degi = nullptr; cudaGetSymbolAddress((void**)&degi, g_degi);
    int*   off  = nullptr; cudaGetSymbolAddress((void**)&off,  g_off);
    int*   cur  = nullptr; cudaGetSymbolAddress((void**)&cur,  g_cur);
    int*   csrc = nullptr; cudaGetSymbolAddress((void**)&csrc, g_csrc);
    int*   bsum = nullptr; cudaGetSymbolAddress((void**)&bsum, g_bsum);
    float* sums = nullptr; cudaGetSymbolAddress((void**)&sums, g_sums);
    float* cnt  = nullptr; cudaGetSymbolAddress((void**)&cnt,  g_cnt);

    cudaFuncSetAttribute(gemm_tc_k<0>, cudaFuncAttributeMaxDynamicSharedMemorySize,
                         GEMM_SMEM_BYTES);
    cudaFuncSetAttribute(gemm_tc_k<1>, cudaFuncAttributeMaxDynamicSharedMemorySize,
                         GEMM_SMEM_BYTES);

    const int T = 256;
    const int GB = (NN + 127) / 128;   // 313 gemm CTAs

    // setup: degrees, dinv, graph-size histogram, CSC build
    zero_k<<<(NN + T - 1) / T, T>>>(degi, cur, sums, cnt);
    count_k<<<(EE + T - 1) / T, T>>>(col, degi);
    dinv_cnt_k<<<(NN + T - 1) / T, T>>>(degi, dinv, batch, cnt);
    scan1_k<<<SCAN_B, SCAN_T>>>(degi, off, bsum);
    scan2_k<<<1, 32>>>(bsum);
    scan3_k<<<SCAN_B, SCAN_T>>>(off, bsum);
    scatter_k<<<(EE + T - 1) / T, T>>>(row, col, off, cur, csrc);

    // layer 1
    gemm_tc_k<0><<<GB, 512, GEMM_SMEM_BYTES>>>(x, W1, bufA);
    agg_node_k<0><<<(NN * 32 + T - 1) / T, T>>>(bufA, dinv, off, csrc, b1, bufB, nullptr, nullptr);

    // layer 2 (pool fused into aggregation)
    gemm_tc_k<1><<<GB, 512, GEMM_SMEM_BYTES>>>(bufB, W2, bufA);
    agg_node_k<1><<<(NN * 32 + T - 1) / T, T>>>(bufA, dinv, off, csrc, b2, nullptr, batch, sums);

    // head
    head_k<<<GG, 32>>>(sums, cnt, Wfc, bfc, out);
}

// round 14
// speedup vs baseline: 1.2536x; 1.2536x over previous
#include <cuda_runtime.h>
#include <cuda_bf16.h>
#include <cstdint>

#define NN     40000
#define EE     640000
#define HH     128
#define GG     256
#define OUTD   10

#define SCAN_T 1024
#define SCAN_B ((NN + SCAN_T - 1) / SCAN_T)   // 40 blocks

// GEMM geometry: 512 threads, 128x128 tile, warp tile 32x32 (2 m x 4 n of m16n8k16)
// All operands pre-converted to packed bf16x2 planes in smem, 68-word stride.
#define PL 68                                  // words per row (64 k-pairs + pad)
#define PLANE_WORDS (128 * PL)                 // 8704 words = 34,816 B
#define GEMM_SMEM_BYTES (4 * PLANE_WORDS * 4)  // Whi,Wlo,Ahi,Alo = 139,264 B

// ---------------- scratch (no allocations allowed) ----------------
__device__ float g_bufA[(size_t)NN * HH];   // xw
__device__ float g_bufB[(size_t)NN * HH];   // h1
__device__ float g_dinv[NN];
__device__ int   g_degi[NN];
__device__ int   g_off[NN + 1];
__device__ int   g_cur[NN];
__device__ int   g_csrc[EE];
__device__ int   g_bsum[SCAN_B];
__device__ float g_sums[GG * HH];
__device__ float g_cnt[GG];

// ---------------- bf16 helpers ----------------
// pack two floats -> bf16x2 word (f0 in low half = even k, f1 in high half = odd k)
__device__ __forceinline__ unsigned pack_bf16x2(float f0, float f1) {
    unsigned r;
    asm("cvt.rn.bf16x2.f32 %0, %1, %2;" : "=r"(r) : "f"(f1), "f"(f0));
    return r;
}
__device__ __forceinline__ float bf_lo_f(unsigned w) { return __uint_as_float(w << 16); }
__device__ __forceinline__ float bf_hi_f(unsigned w) { return __uint_as_float(w & 0xffff0000u); }

__device__ __forceinline__ void mma_bf16(float c[4], const unsigned a[4], const unsigned b[2]) {
    asm volatile(
        "mma.sync.aligned.m16n8k16.row.col.f32.bf16.bf16.f32 "
        "{%0,%1,%2,%3}, {%4,%5,%6,%7}, {%8,%9}, {%0,%1,%2,%3};"
        : "+f"(c[0]), "+f"(c[1]), "+f"(c[2]), "+f"(c[3])
        : "r"(a[0]), "r"(a[1]), "r"(a[2]), "r"(a[3]), "r"(b[0]), "r"(b[1]));
}

// ---------------- setup ----------------
__global__ void zero_k(int* degi, int* cur, float* sums, float* cnt) {
    int i = blockIdx.x * blockDim.x + threadIdx.x;
    if (i < NN) { degi[i] = 0; cur[i] = 0; }
    if (i < GG * HH) sums[i] = 0.0f;
    if (i < GG) cnt[i] = 0.0f;
}

__global__ void count_k(const int* __restrict__ col, int* degi) {
    int e = blockIdx.x * blockDim.x + threadIdx.x;
    if (e < EE) atomicAdd(&degi[col[e]], 1);
}

__global__ void dinv_cnt_k(const int* __restrict__ degi, float* __restrict__ dinv,
                           const int* __restrict__ batch, float* cnt) {
    int i = blockIdx.x * blockDim.x + threadIdx.x;
    if (i < NN) {
        dinv[i] = rsqrtf((float)(degi[i] + 1));   // +1 self-loop
        atomicAdd(&cnt[batch[i]], 1.0f);
    }
}

// ---------------- multi-block exclusive scan ----------------
__global__ __launch_bounds__(SCAN_T)
void scan1_k(const int* __restrict__ deg, int* __restrict__ off, int* __restrict__ bsum) {
    __shared__ int wsum[32];
    int tid = threadIdx.x, lane = tid & 31, wid = tid >> 5;
    int i = blockIdx.x * SCAN_T + tid;
    int v = (i < NN) ? deg[i] : 0;
    int x = v;
    #pragma unroll
    for (int o = 1; o < 32; o <<= 1) {
        int t = __shfl_up_sync(0xffffffffu, x, o);
        if (lane >= o) x += t;
    }
    if (lane == 31) wsum[wid] = x;
    __syncthreads();
    if (wid == 0) {
        int y = wsum[lane];
        #pragma unroll
        for (int o = 1; o < 32; o <<= 1) {
            int t = __shfl_up_sync(0xffffffffu, y, o);
            if (lane >= o) y += t;
        }
        wsum[lane] = y;
    }
    __syncthreads();
    int incl = x + (wid ? wsum[wid - 1] : 0);
    if (i < NN) off[i + 1] = incl;
    if (tid == SCAN_T - 1) bsum[blockIdx.x] = incl;
}

__global__ void scan2_k(int* __restrict__ bsum) {
    int lane = threadIdx.x & 31;
    int i0 = lane, i1 = lane + 32;
    int v0 = (i0 < SCAN_B) ? bsum[i0] : 0;
    int v1 = (i1 < SCAN_B) ? bsum[i1] : 0;
    int x0 = v0;
    #pragma unroll
    for (int o = 1; o < 32; o <<= 1) {
        int t = __shfl_up_sync(0xffffffffu, x0, o);
        if (lane >= o) x0 += t;
    }
    int tot0 = __shfl_sync(0xffffffffu, x0, 31);
    int x1 = v1;
    #pragma unroll
    for (int o = 1; o < 32; o <<= 1) {
        int t = __shfl_up_sync(0xffffffffu, x1, o);
        if (lane >= o) x1 += t;
    }
    if (i0 < SCAN_B) bsum[i0] = x0 - v0;
    if (i1 < SCAN_B) bsum[i1] = x1 - v1 + tot0;
}

__global__ __launch_bounds__(SCAN_T)
void scan3_k(int* __restrict__ off, const int* __restrict__ bsum) {
    int i = blockIdx.x * SCAN_T + threadIdx.x;
    if (i == 0) off[0] = 0;
    if (i < NN) off[i + 1] += bsum[blockIdx.x];
}

__global__ void scatter_k(const int* __restrict__ row, const int* __restrict__ col,
                          const int* __restrict__ off, int* cur, int* __restrict__ csrc) {
    int e = blockIdx.x * blockDim.x + threadIdx.x;
    if (e >= EE) return;
    int c = col[e];
    int pos = off[c] + atomicAdd(&cur[c], 1);
    csrc[pos] = row[e];
}

// ---------------- 3-term bf16 tensor-core GEMM: xw = (relu?)A @ W ----------------
template <int RELU>
__global__ __launch_bounds__(512)
void gemm_tc_k(const float* __restrict__ A, const float* __restrict__ W,
               float* __restrict__ xw) {
    extern __shared__ unsigned usmem[];
    unsigned* Whi = usmem;                     // [128 n][PL] bf16x2 k-pairs
    unsigned* Wlo = usmem + PLANE_WORDS;
    unsigned* Ahi = usmem + 2 * PLANE_WORDS;   // [128 m][PL]
    unsigned* Alo = usmem + 3 * PLANE_WORDS;

    const int tid  = threadIdx.x;
    const int warp = tid >> 5;
    const int lane = tid & 31;
    const int gid  = lane >> 2;                 // 0..7
    const int tig  = lane & 3;                  // 0..3
    const int mBase = (warp & 3) * 32;
    const int nBase = (warp >> 2) * 32;
    const int rowG  = blockIdx.x * 128;

    // ---- prologue: W -> transposed bf16x2 hi/lo planes  [n][kp] ----
    #pragma unroll
    for (int i = 0; i < 16; i++) {
        int id = tid + i * 512;                 // 0..8191
        int n  = id & 127;
        int kp = id >> 7;                       // 0..63
        float f0 = __ldg(&W[(2 * kp)     * 128 + n]);
        float f1 = __ldg(&W[(2 * kp + 1) * 128 + n]);
        unsigned whi = pack_bf16x2(f0, f1);
        float r0 = f0 - bf_lo_f(whi);
        float r1 = f1 - bf_hi_f(whi);
        Whi[n * PL + kp] = whi;
        Wlo[n * PL + kp] = pack_bf16x2(r0, r1);
    }
    // ---- prologue: A -> bf16x2 hi/lo planes [m][kp] (relu folded) ----
    #pragma unroll
    for (int i = 0; i < 8; i++) {
        int id = tid + i * 512;                 // 0..4095 float4 units
        int m  = id >> 5;
        int c4 = (id & 31) * 4;
        int gr = rowG + m; if (gr > NN - 1) gr = NN - 1;
        float4 v = *reinterpret_cast<const float4*>(&A[(size_t)gr * HH + c4]);
        if (RELU) {
            v.x = fmaxf(v.x, 0.0f); v.y = fmaxf(v.y, 0.0f);
            v.z = fmaxf(v.z, 0.0f); v.w = fmaxf(v.w, 0.0f);
        }
        unsigned h0 = pack_bf16x2(v.x, v.y);
        unsigned h1 = pack_bf16x2(v.z, v.w);
        unsigned l0 = pack_bf16x2(v.x - bf_lo_f(h0), v.y - bf_hi_f(h0));
        unsigned l1 = pack_bf16x2(v.z - bf_lo_f(h1), v.w - bf_hi_f(h1));
        int kp = c4 >> 1;                       // even
        *reinterpret_cast<uint2*>(&Ahi[m * PL + kp]) = make_uint2(h0, h1);
        *reinterpret_cast<uint2*>(&Alo[m * PL + kp]) = make_uint2(l0, l1);
    }
    __syncthreads();

    float c[2][4][4];
    #pragma unroll
    for (int mt = 0; mt < 2; mt++)
        #pragma unroll
        for (int nt = 0; nt < 4; nt++)
            #pragma unroll
            for (int j = 0; j < 4; j++) c[mt][nt][j] = 0.0f;

    // ---- mainloop: 8 k-steps of 16, no syncs ----
    #pragma unroll
    for (int ks = 0; ks < 8; ks++) {
        int kb = ks * 8;                        // k-pair base
        unsigned ah[2][4], al[2][4];
        #pragma unroll
        for (int mt = 0; mt < 2; mt++) {
            int r0 = mBase + mt * 16;
            ah[mt][0] = Ahi[(r0 + gid)     * PL + kb + tig];
            ah[mt][1] = Ahi[(r0 + gid + 8) * PL + kb + tig];
            ah[mt][2] = Ahi[(r0 + gid)     * PL + kb + tig + 4];
            ah[mt][3] = Ahi[(r0 + gid + 8) * PL + kb + tig + 4];
            al[mt][0] = Alo[(r0 + gid)     * PL + kb + tig];
            al[mt][1] = Alo[(r0 + gid + 8) * PL + kb + tig];
            al[mt][2] = Alo[(r0 + gid)     * PL + kb + tig + 4];
            al[mt][3] = Alo[(r0 + gid + 8) * PL + kb + tig + 4];
        }
        #pragma unroll
        for (int nt = 0; nt < 4; nt++) {
            int n0 = nBase + nt * 8;
            unsigned bh[2], bl[2];
            bh[0] = Whi[(n0 + gid) * PL + kb + tig];
            bh[1] = Whi[(n0 + gid) * PL + kb + tig + 4];
            bl[0] = Wlo[(n0 + gid) * PL + kb + tig];
            bl[1] = Wlo[(n0 + gid) * PL + kb + tig + 4];
            #pragma unroll
            for (int mt = 0; mt < 2; mt++) {
                mma_bf16(c[mt][nt], ah[mt], bh);   // hi*hi
                mma_bf16(c[mt][nt], al[mt], bh);   // lo*hi
                mma_bf16(c[mt][nt], ah[mt], bl);   // hi*lo
            }
        }
    }

    // ---- epilogue ----
    #pragma unroll
    for (int mt = 0; mt < 2; mt++) {
        #pragma unroll
        for (int nt = 0; nt < 4; nt++) {
            int r0  = rowG + mBase + mt * 16 + gid;
            int col = nBase + nt * 8 + tig * 2;
            if (r0 < NN)
                *reinterpret_cast<float2*>(&xw[(size_t)r0 * HH + col]) =
                    make_float2(c[mt][nt][0], c[mt][nt][1]);
            int r1 = r0 + 8;
            if (r1 < NN)
                *reinterpret_cast<float2*>(&xw[(size_t)r1 * HH + col]) =
                    make_float2(c[mt][nt][2], c[mt][nt][3]);
        }
    }
}

// ---------------- node aggregation (warp per node, register accumulate) ----------------
template <int POOL>
__global__ __launch_bounds__(256)
void agg_node_k(const float* __restrict__ xw, const float* __restrict__ dinv,
                const int* __restrict__ off, const int* __restrict__ csrc,
                const float* __restrict__ bias, float* __restrict__ h,
                const int* __restrict__ batch, float* __restrict__ sums) {
    int n    = (blockIdx.x * blockDim.x + threadIdx.x) >> 5;
    int lane = threadIdx.x & 31;
    if (n >= NN) return;

    float dn = __ldg(&dinv[n]);
    float4 acc = *reinterpret_cast<const float4*>(xw + (size_t)n * HH + lane * 4);
    acc.x *= dn; acc.y *= dn; acc.z *= dn; acc.w *= dn;

    int p = __ldg(&off[n]);
    int e = __ldg(&off[n + 1]);

    for (; p + 1 < e; p += 2) {
        int s0 = __ldg(&csrc[p]);
        int s1 = __ldg(&csrc[p + 1]);
        float w0 = __ldg(&dinv[s0]);
        float w1 = __ldg(&dinv[s1]);
        float4 v0 = *reinterpret_cast<const float4*>(xw + (size_t)s0 * HH + lane * 4);
        float4 v1 = *reinterpret_cast<const float4*>(xw + (size_t)s1 * HH + lane * 4);
        acc.x += v0.x * w0 + v1.x * w1;
        acc.y += v0.y * w0 + v1.y * w1;
        acc.z += v0.z * w0 + v1.z * w1;
        acc.w += v0.w * w0 + v1.w * w1;
    }
    if (p < e) {
        int s0 = __ldg(&csrc[p]);
        float w0 = __ldg(&dinv[s0]);
        float4 v0 = *reinterpret_cast<const float4*>(xw + (size_t)s0 * HH + lane * 4);
        acc.x += v0.x * w0; acc.y += v0.y * w0;
        acc.z += v0.z * w0; acc.w += v0.w * w0;
    }

    float4 b = *reinterpret_cast<const float4*>(bias + lane * 4);
    float4 o;
    o.x = fmaf(acc.x, dn, b.x); o.y = fmaf(acc.y, dn, b.y);
    o.z = fmaf(acc.z, dn, b.z); o.w = fmaf(acc.w, dn, b.w);

    if (POOL) {
        o.x = fmaxf(o.x, 0.0f); o.y = fmaxf(o.y, 0.0f);
        o.z = fmaxf(o.z, 0.0f); o.w = fmaxf(o.w, 0.0f);
        int g = __ldg(&batch[n]);
        float* d = sums + (size_t)g * HH + lane * 4;
        asm volatile("red.global.add.v4.f32 [%0], {%1,%2,%3,%4};"
                     :: "l"(d), "f"(o.x), "f"(o.y), "f"(o.z), "f"(o.w) : "memory");
    } else {
        *reinterpret_cast<float4*>(h + (size_t)n * HH + lane * 4) = o;
    }
}

// ---------------- head: mean -> FC -> log_softmax ----------------
__global__ void head_k(const float* __restrict__ sums, const float* __restrict__ cnt,
                       const float* __restrict__ Wfc, const float* __restrict__ bfc,
                       float* __restrict__ out) {
    int g = blockIdx.x;
    int lane = threadIdx.x;
    float inv = 1.0f / fmaxf(cnt[g], 1.0f);
    float p[4];
    #pragma unroll
    for (int i = 0; i < 4; i++)
        p[i] = sums[(size_t)g * HH + lane * 4 + i] * inv;

    float logits[OUTD];
    #pragma unroll
    for (int o = 0; o < OUTD; o++) {
        float s = 0.0f;
        #pragma unroll
        for (int i = 0; i < 4; i++)
            s = fmaf(p[i], __ldg(&Wfc[(size_t)(lane * 4 + i) * OUTD + o]), s);
        #pragma unroll
        for (int off = 16; off > 0; off >>= 1)
            s += __shfl_xor_sync(0xffffffffu, s, off);
        logits[o] = s + __ldg(&bfc[o]);
    }
    if (lane == 0) {
        float m = logits[0];
        #pragma unroll
        for (int o = 1; o < OUTD; o++) m = fmaxf(m, logits[o]);
        float lse = 0.0f;
        #pragma unroll
        for (int o = 0; o < OUTD; o++) lse += expf(logits[o] - m);
        lse = logf(lse);
        #pragma unroll
        for (int o = 0; o < OUTD; o++)
            out[(size_t)g * OUTD + o] = logits[o] - m - lse;
    }
}

// ---------------- launcher ----------------
extern "C" void kernel_launch(void* const* d_in, const int* in_sizes, int n_in,
                              void* d_out, int out_size) {
    const float* x    = (const float*)d_in[0];
    const int*   ei   = (const int*)d_in[1];
    const int*   batch= (const int*)d_in[2];
    const float* W1   = (const float*)d_in[3];
    const float* b1   = (const float*)d_in[4];
    const float* W2   = (const float*)d_in[5];
    const float* b2   = (const float*)d_in[6];
    const float* Wfc  = (const float*)d_in[7];
    const float* bfc  = (const float*)d_in[8];
    float* out = (float*)d_out;

    const int* row = ei;
    const int* col = ei + EE;

    float* bufA = nullptr; cudaGetSymbolAddress((void**)&bufA, g_bufA);
    float* bufB = nullptr; cudaGetSymbolAddress((void**)&bufB, g_bufB);
    float* dinv = nullptr; cudaGetSymbolAddress((void**)&dinv, g_dinv);
    int*   degi = nullptr; cudaGetSymbolAddress((void**)&degi, g_degi);
    int*   off  = nullptr; cudaGetSymbolAddress((void**)&off,  g_off);
    int*   cur  = nullptr; cudaGetSymbolAddress((void**)&cur,  g_cur);
    int*   csrc = nullptr; cudaGetSymbolAddress((void**)&csrc, g_csrc);
    int*   bsum = nullptr; cudaGetSymbolAddress((void**)&bsum, g_bsum);
    float* sums = nullptr; cudaGetSymbolAddress((void**)&sums, g_sums);
    float* cnt  = nullptr; cudaGetSymbolAddress((void**)&cnt,  g_cnt);

    cudaFuncSetAttribute(gemm_tc_k<0>, cudaFuncAttributeMaxDynamicSharedMemorySize,
                         GEMM_SMEM_BYTES);
    cudaFuncSetAttribute(gemm_tc_k<1>, cudaFuncAttributeMaxDynamicSharedMemorySize,
                         GEMM_SMEM_BYTES);

    const int T = 256;
    const int GB = (NN + 127) / 128;   // 313 gemm CTAs

    // setup: degrees, dinv, graph-size histogram, CSC build
    zero_k<<<(NN + T - 1) / T, T>>>(degi, cur, sums, cnt);
    count_k<<<(EE + T - 1) / T, T>>>(col, degi);
    dinv_cnt_k<<<(NN + T - 1) / T, T>>>(degi, dinv, batch, cnt);
    scan1_k<<<SCAN_B, SCAN_T>>>(degi, off, bsum);
    scan2_k<<<1, 32>>>(bsum);
    scan3_k<<<SCAN_B, SCAN_T>>>(off, bsum);
    scatter_k<<<(EE + T - 1) / T, T>>>(row, col, off, cur, csrc);

    // layer 1
    gemm_tc_k<0><<<GB, 512, GEMM_SMEM_BYTES>>>(x, W1, bufA);
    agg_node_k<0><<<(NN * 32 + T - 1) / T, T>>>(bufA, dinv, off, csrc, b1, bufB, nullptr, nullptr);

    // layer 2 (pool fused into aggregation)
    gemm_tc_k<1><<<GB, 512, GEMM_SMEM_BYTES>>>(bufB, W2, bufA);
    agg_node_k<1><<<(NN * 32 + T - 1) / T, T>>>(bufA, dinv, off, csrc, b2, nullptr, batch, sums);

    // head
    head_k<<<GG, 32>>>(sums, cnt, Wfc, bfc, out);
}